// round 12
// baseline (speedup 1.0000x reference)
#include <cuda_runtime.h>
#include <math.h>

#define HID   2048
#define VOCAB 50257

// Scratch (no cudaMalloc allowed). Static zero-init; counters self-reset.
__device__ float        g_part[2][6][HID];   // [half][gate-row][unit] partial dots
__device__ unsigned int g_unit_cnt[HID];     // per-unit arrival counters (0/1)
__device__ float        g_hnew[HID];
__device__ float        g_logits[VOCAB];
__device__ float        g_sum;

// Prefetch config: last PF_BLOCKS gru blocks each prefetch 32KB of w_out into
// L2 with evict_last priority (pinned against the gru's own streaming).
#define PF_FIRST  1536
#define PF_BLOCKS (4096 - PF_FIRST)   // 2560 blocks x 32KB = 80 MB

// ---------------------------------------------------------------------------
// Kernel 1: GRU gate GEMVs, split-K x2. Block b -> (unit u = b>>1, half=b&1).
// Weight demand loads use __ldcs (cache-streaming, use-once); late blocks
// prefetch the front of w_out into L2 with evict_last, in DRAM-idle time.
// ---------------------------------------------------------------------------
__global__ void __launch_bounds__(256, 6) gru_kernel(
    const int*   __restrict__ idx,
    const float* __restrict__ hidden,
    const float* __restrict__ embed,
    const float* __restrict__ w_ih,
    const float* __restrict__ w_hh,
    const float* __restrict__ b_ih,
    const float* __restrict__ b_hh,
    const float* __restrict__ w_out,
    float*       __restrict__ hnew_out)   // may be null
{
    const int tid  = threadIdx.x;
    const int lane = tid & 31;
    const int warp = tid >> 5;
    const int u    = blockIdx.x >> 1;
    const int half = blockIdx.x & 1;

    const int token = idx[0];
    const int k = half * 256 + tid;        // float4 index within the row

    // x/h: shared across many blocks -> default policy (L2 reuse wanted).
    const float4 xv = ((const float4*)(embed + (size_t)token * HID))[k];
    const float4 hv = ((const float4*)hidden)[k];

    // Weights: use-once streaming -> __ldcs (evict-first semantics).
    const float4 wi_r = __ldcs((const float4*)(w_ih + (size_t)( u         ) * HID) + k);
    const float4 wi_z = __ldcs((const float4*)(w_ih + (size_t)( HID   + u ) * HID) + k);
    const float4 wi_n = __ldcs((const float4*)(w_ih + (size_t)( 2*HID + u ) * HID) + k);
    const float4 wh_r = __ldcs((const float4*)(w_hh + (size_t)( u         ) * HID) + k);
    const float4 wh_z = __ldcs((const float4*)(w_hh + (size_t)( HID   + u ) * HID) + k);
    const float4 wh_n = __ldcs((const float4*)(w_hh + (size_t)( 2*HID + u ) * HID) + k);

    float a[6];
    a[0] = wi_r.x*xv.x + wi_r.y*xv.y + wi_r.z*xv.z + wi_r.w*xv.w;
    a[1] = wi_z.x*xv.x + wi_z.y*xv.y + wi_z.z*xv.z + wi_z.w*xv.w;
    a[2] = wi_n.x*xv.x + wi_n.y*xv.y + wi_n.z*xv.z + wi_n.w*xv.w;
    a[3] = wh_r.x*hv.x + wh_r.y*hv.y + wh_r.z*hv.z + wh_r.w*hv.w;
    a[4] = wh_z.x*hv.x + wh_z.y*hv.y + wh_z.z*hv.z + wh_z.w*hv.w;
    a[5] = wh_n.x*hv.x + wh_n.y*hv.y + wh_n.z*hv.z + wh_n.w*hv.w;

    #pragma unroll
    for (int o = 16; o; o >>= 1) {
        #pragma unroll
        for (int j = 0; j < 6; j++)
            a[j] += __shfl_xor_sync(0xffffffffu, a[j], o);
    }

    // Fire-and-forget L2 prefetch of w_out, pinned with evict_last.
    if (blockIdx.x >= PF_FIRST) {
        const char* p = (const char*)w_out
                      + (size_t)(blockIdx.x - PF_FIRST) * 32768 + (size_t)tid * 128;
        asm volatile("prefetch.global.L2::evict_last [%0];" :: "l"(p));
    }

    __shared__ float s[8][6];
    if (lane == 0) {
        #pragma unroll
        for (int j = 0; j < 6; j++) s[warp][j] = a[j];
    }
    __syncthreads();

    if (tid == 0) {
        float t[6];
        #pragma unroll
        for (int j = 0; j < 6; j++) {
            float v = s[0][j];
            #pragma unroll
            for (int w = 1; w < 8; w++) v += s[w][j];
            t[j] = v;
        }
        #pragma unroll
        for (int j = 0; j < 6; j++) g_part[half][j][u] = t[j];
        __threadfence();                         // release partial stores
        const unsigned int prev = atomicAdd(&g_unit_cnt[u], 1u);

        if (prev == 1u) {                        // second arriver combines
            __threadfence();                     // acquire partner's stores
            const int oh = 1 - half;
            const float gir = t[0] + g_part[oh][0][u] + b_ih[u];
            const float giz = t[1] + g_part[oh][1][u] + b_ih[HID + u];
            const float gin = t[2] + g_part[oh][2][u] + b_ih[2*HID + u];
            const float ghr = t[3] + g_part[oh][3][u] + b_hh[u];
            const float ghz = t[4] + g_part[oh][4][u] + b_hh[HID + u];
            const float ghn = t[5] + g_part[oh][5][u] + b_hh[2*HID + u];

            const float r  = 1.0f / (1.0f + expf(-(gir + ghr)));
            const float z  = 1.0f / (1.0f + expf(-(giz + ghz)));
            const float n  = tanhf(gin + r * ghn);
            const float hn = (1.0f - z) * n + z * hidden[u];

            g_hnew[u] = hn;
            if (hnew_out) hnew_out[u] = hn;

            g_unit_cnt[u] = 0u;                  // reset for next graph replay
            if (u == 0) g_sum = 0.0f;            // logits adds are stream-ordered later
        }
    }
}

// ---------------------------------------------------------------------------
// Kernel 2: logits = relu(w_out @ h_new + b_out). Warp-per-row, 8 rows/block.
// No max pass: post-ReLU logits are >= 0 and small, exp cannot overflow.
// Each block atomically accumulates its partial sum of exp(l) into g_sum.
// ---------------------------------------------------------------------------
__global__ void __launch_bounds__(256) logits_kernel(
    const float* __restrict__ w_out,
    const float* __restrict__ b_out)
{
    const int lane = threadIdx.x & 31;
    const int warp = threadIdx.x >> 5;
    const int row  = blockIdx.x * 8 + warp;

    float e = 0.0f;                      // this warp's exp(l), 0 if row invalid
    if (row < VOCAB) {
        const float4* w4 = (const float4*)(w_out + (size_t)row * HID);
        const float4* h4 = (const float4*)g_hnew;
        float acc = 0.0f;
        #pragma unroll
        for (int j = 0; j < 16; j++) {
            const int k = lane + 32 * j;
            const float4 w = w4[k];
            const float4 h = h4[k];
            acc += w.x*h.x + w.y*h.y + w.z*h.z + w.w*h.w;
        }
        #pragma unroll
        for (int o = 16; o; o >>= 1)
            acc += __shfl_xor_sync(0xffffffffu, acc, o);
        if (lane == 0) {
            const float l = fmaxf(acc + b_out[row], 0.0f);
            g_logits[row] = l;
            e = expf(l);
        }
    }

    __shared__ float s_exp[8];
    if (lane == 0) s_exp[warp] = e;
    __syncthreads();
    if (threadIdx.x == 0) {
        float t = s_exp[0];
        #pragma unroll
        for (int w = 1; w < 8; w++) t += s_exp[w];
        atomicAdd(&g_sum, t);
    }
}

// ---------------------------------------------------------------------------
// Kernel 3: finalize. out[v] = l[v] - log(sum). Stream order guarantees all
// g_sum contributions are visible.
// ---------------------------------------------------------------------------
__global__ void __launch_bounds__(1024) finalize_kernel(float* __restrict__ out)
{
    __shared__ float s_ls;
    if (threadIdx.x == 0) s_ls = logf(g_sum);
    __syncthreads();
    const int v = blockIdx.x * 1024 + threadIdx.x;
    if (v < VOCAB)
        out[v] = g_logits[v] - s_ls;
}

// ---------------------------------------------------------------------------
extern "C" void kernel_launch(void* const* d_in, const int* in_sizes, int n_in,
                              void* d_out, int out_size)
{
    const int*   idx    = (const int*)  d_in[0];
    const float* hidden = (const float*)d_in[1];
    const float* embed  = (const float*)d_in[2];
    const float* w_ih   = (const float*)d_in[3];
    const float* w_hh   = (const float*)d_in[4];
    const float* b_ih   = (const float*)d_in[5];
    const float* b_hh   = (const float*)d_in[6];
    const float* w_out  = (const float*)d_in[7];
    const float* b_out  = (const float*)d_in[8];

    float* out = (float*)d_out;
    float* hnew_out = (out_size >= VOCAB + HID) ? (out + VOCAB) : nullptr;

    gru_kernel<<<2 * HID, 256>>>(idx, hidden, embed, w_ih, w_hh,
                                 b_ih, b_hh, w_out, hnew_out);
    logits_kernel<<<(VOCAB + 7) / 8, 256>>>(w_out, b_out);
    finalize_kernel<<<(VOCAB + 1023) / 1024, 1024>>>(out);
}

// round 13
// speedup vs baseline: 1.0202x; 1.0202x over previous
#include <cuda_runtime.h>
#include <math.h>

#define HID   2048
#define VOCAB 50257

#define NLOG_BLOCKS ((VOCAB + 7) / 8)     // 6283 logits blocks
#define KFIN   444                        // last-K arrivers finalize (< 888 residency)
#define SLICE  114                        // ceil(VOCAB / KFIN); 444*114 = 50616 >= VOCAB

// Scratch (no cudaMalloc allowed). Static zero-init; counters self-reset.
__device__ float        g_part[2][6][HID];   // [half][gate-row][unit] partial dots
__device__ unsigned int g_unit_cnt[HID];     // per-unit arrival counters (0/1)
__device__ float        g_hnew[HID];
__device__ float        g_logits[VOCAB];
__device__ float        g_sum;
__device__ unsigned int g_cnt;               // logits-block arrival counter
__device__ unsigned int g_cnt2;              // finalizer completion counter

// ---------------------------------------------------------------------------
// Kernel 1: GRU gate GEMVs, split-K x2 (exact R9 shape: 23.6us measured).
// Block b -> (unit u = b>>1, half = b&1). Second arriver per unit combines
// partials, runs the gate math for its unit, resets its counter.
// ---------------------------------------------------------------------------
__global__ void __launch_bounds__(256, 6) gru_kernel(
    const int*   __restrict__ idx,
    const float* __restrict__ hidden,
    const float* __restrict__ embed,
    const float* __restrict__ w_ih,
    const float* __restrict__ w_hh,
    const float* __restrict__ b_ih,
    const float* __restrict__ b_hh,
    float*       __restrict__ hnew_out)   // may be null
{
    const int tid  = threadIdx.x;
    const int lane = tid & 31;
    const int warp = tid >> 5;
    const int u    = blockIdx.x >> 1;
    const int half = blockIdx.x & 1;

    const int token = idx[0];
    const int k = half * 256 + tid;        // float4 index within the row

    // 8 independent loads, front-batched.
    const float4 xv   = ((const float4*)(embed + (size_t)token * HID))[k];
    const float4 hv   = ((const float4*)hidden)[k];
    const float4 wi_r = ((const float4*)(w_ih + (size_t)( u         ) * HID))[k];
    const float4 wi_z = ((const float4*)(w_ih + (size_t)( HID   + u ) * HID))[k];
    const float4 wi_n = ((const float4*)(w_ih + (size_t)( 2*HID + u ) * HID))[k];
    const float4 wh_r = ((const float4*)(w_hh + (size_t)( u         ) * HID))[k];
    const float4 wh_z = ((const float4*)(w_hh + (size_t)( HID   + u ) * HID))[k];
    const float4 wh_n = ((const float4*)(w_hh + (size_t)( 2*HID + u ) * HID))[k];

    float a[6];
    a[0] = wi_r.x*xv.x + wi_r.y*xv.y + wi_r.z*xv.z + wi_r.w*xv.w;
    a[1] = wi_z.x*xv.x + wi_z.y*xv.y + wi_z.z*xv.z + wi_z.w*xv.w;
    a[2] = wi_n.x*xv.x + wi_n.y*xv.y + wi_n.z*xv.z + wi_n.w*xv.w;
    a[3] = wh_r.x*hv.x + wh_r.y*hv.y + wh_r.z*hv.z + wh_r.w*hv.w;
    a[4] = wh_z.x*hv.x + wh_z.y*hv.y + wh_z.z*hv.z + wh_z.w*hv.w;
    a[5] = wh_n.x*hv.x + wh_n.y*hv.y + wh_n.z*hv.z + wh_n.w*hv.w;

    #pragma unroll
    for (int o = 16; o; o >>= 1) {
        #pragma unroll
        for (int j = 0; j < 6; j++)
            a[j] += __shfl_xor_sync(0xffffffffu, a[j], o);
    }

    __shared__ float s[8][6];
    if (lane == 0) {
        #pragma unroll
        for (int j = 0; j < 6; j++) s[warp][j] = a[j];
    }
    __syncthreads();

    if (tid == 0) {
        float t[6];
        #pragma unroll
        for (int j = 0; j < 6; j++) {
            float v = s[0][j];
            #pragma unroll
            for (int w = 1; w < 8; w++) v += s[w][j];
            t[j] = v;
        }
        #pragma unroll
        for (int j = 0; j < 6; j++) g_part[half][j][u] = t[j];
        __threadfence();                         // release partial stores
        const unsigned int prev = atomicAdd(&g_unit_cnt[u], 1u);

        if (prev == 1u) {                        // second arriver combines
            __threadfence();                     // acquire partner's stores
            const int oh = 1 - half;
            const float gir = t[0] + g_part[oh][0][u] + b_ih[u];
            const float giz = t[1] + g_part[oh][1][u] + b_ih[HID + u];
            const float gin = t[2] + g_part[oh][2][u] + b_ih[2*HID + u];
            const float ghr = t[3] + g_part[oh][3][u] + b_hh[u];
            const float ghz = t[4] + g_part[oh][4][u] + b_hh[HID + u];
            const float ghn = t[5] + g_part[oh][5][u] + b_hh[2*HID + u];

            const float r  = 1.0f / (1.0f + expf(-(gir + ghr)));
            const float z  = 1.0f / (1.0f + expf(-(giz + ghz)));
            const float n  = tanhf(gin + r * ghn);
            const float hn = (1.0f - z) * n + z * hidden[u];

            g_hnew[u] = hn;
            if (hnew_out) hnew_out[u] = hn;

            g_unit_cnt[u] = 0u;                  // reset for next graph replay
            if (u == 0) g_sum = 0.0f;            // logits adds are stream-ordered later
        }
    }
}

// ---------------------------------------------------------------------------
// Kernel 2: logits + inline log-softmax finalize.
// Warp-per-row, 8 rows/block (87%-of-HBM shape). No max pass: post-ReLU
// logits are >= 0 and small, exp cannot overflow. Each block adds its exp
// partial to g_sum and takes an arrival rank. The last KFIN arrivers (all
// resident by construction, KFIN < the 888 residency guaranteed by
// __launch_bounds__(256, 6)) spin until everyone has arrived, then each
// writes a SLICE-element chunk of out = l - log(sum). No third kernel.
// ---------------------------------------------------------------------------
__global__ void __launch_bounds__(256, 6) logits_kernel(
    const float* __restrict__ w_out,
    const float* __restrict__ b_out,
    float*       __restrict__ out)
{
    const int tid  = threadIdx.x;
    const int lane = tid & 31;
    const int warp = tid >> 5;
    const int row  = blockIdx.x * 8 + warp;

    float e = 0.0f;                      // this warp's exp(l), 0 if row invalid
    if (row < VOCAB) {
        const float4* w4 = (const float4*)(w_out + (size_t)row * HID);
        const float4* h4 = (const float4*)g_hnew;
        float acc = 0.0f;
        #pragma unroll
        for (int j = 0; j < 16; j++) {
            const int k = lane + 32 * j;
            const float4 w = w4[k];
            const float4 h = h4[k];
            acc += w.x*h.x + w.y*h.y + w.z*h.z + w.w*h.w;
        }
        #pragma unroll
        for (int o = 16; o; o >>= 1)
            acc += __shfl_xor_sync(0xffffffffu, acc, o);
        if (lane == 0) {
            const float l = fmaxf(acc + b_out[row], 0.0f);
            g_logits[row] = l;
            e = expf(l);
        }
    }

    __shared__ float        s_exp[8];
    __shared__ unsigned int s_rank;
    __shared__ float        s_ls;

    if (lane == 0) s_exp[warp] = e;
    __syncthreads();                     // orders g_logits stores before fence
    if (tid == 0) {
        float t = s_exp[0];
        #pragma unroll
        for (int w = 1; w < 8; w++) t += s_exp[w];
        atomicAdd(&g_sum, t);
        __threadfence();                 // release g_sum add + g_logits stores
        s_rank = atomicAdd(&g_cnt, 1u);  // arrival rank
    }
    __syncthreads();

    if (s_rank >= (unsigned int)(NLOG_BLOCKS - KFIN)) {
        // We are one of the last KFIN arrivers: already resident, safe to spin.
        if (tid == 0) {
            volatile unsigned int* c = &g_cnt;
            while (*c < (unsigned int)NLOG_BLOCKS) { __nanosleep(64); }
            __threadfence();             // acquire all g_logits / g_sum
            s_ls = logf(g_sum);
        }
        __syncthreads();

        const float logsum = s_ls;
        const int   slice  = (int)s_rank - (NLOG_BLOCKS - KFIN);
        const int   base   = slice * SLICE;
        if (tid < SLICE) {
            const int v = base + tid;
            if (v < VOCAB)
                out[v] = g_logits[v] - logsum;
        }

        // Reset counters for the next graph replay (last finalizer only).
        __syncthreads();
        if (tid == 0) {
            if (atomicAdd(&g_cnt2, 1u) == KFIN - 1u) {
                g_cnt2 = 0u;
                __threadfence();
                g_cnt = 0u;
            }
        }
    }
}

// ---------------------------------------------------------------------------
extern "C" void kernel_launch(void* const* d_in, const int* in_sizes, int n_in,
                              void* d_out, int out_size)
{
    const int*   idx    = (const int*)  d_in[0];
    const float* hidden = (const float*)d_in[1];
    const float* embed  = (const float*)d_in[2];
    const float* w_ih   = (const float*)d_in[3];
    const float* w_hh   = (const float*)d_in[4];
    const float* b_ih   = (const float*)d_in[5];
    const float* b_hh   = (const float*)d_in[6];
    const float* w_out  = (const float*)d_in[7];
    const float* b_out  = (const float*)d_in[8];

    float* out = (float*)d_out;
    float* hnew_out = (out_size >= VOCAB + HID) ? (out + VOCAB) : nullptr;

    gru_kernel<<<2 * HID, 256>>>(idx, hidden, embed, w_ih, w_hh,
                                 b_ih, b_hh, hnew_out);
    logits_kernel<<<NLOG_BLOCKS, 256>>>(w_out, b_out, out);
}